// round 15
// baseline (speedup 1.0000x reference)
#include <cuda_runtime.h>
#include <math.h>
#include <stdint.h>

// Problem constants
#define TK   16384
#define HD   7168
#define NE   256
#define BT   8              // tokens per CTA
#define BK   32             // k per stage (= one fold chunk)
#define NST  (HD / BK)      // 224 stages
#define NBUF 3              // cp.async ring depth

// smem floats: B ring [3][32][256] + A ring [3][32][9]
#define B_ST   (BK * NE)                  // 8192 floats / stage
#define A_ROW  9
#define A_ST   (BK * A_ROW)               // 288
#define SMEM_FLOATS (NBUF * (B_ST + A_ST))   // 25440 -> 101760 B

static __device__ float g_Wt[(size_t)HD * NE];   // W transposed [k][e], 7.3 MB

// ---------------------------------------------------------------------------
#define FMA2(c, a, b) \
    asm("fma.rn.f32x2 %0, %1, %2, %0;" : "+l"(c) : "l"(a), "l"(b))
#define ADD2(c, s) \
    asm("add.rn.f32x2 %0, %1, %0;" : "+l"(c) : "l"(s))
#define PACK2(o, f) \
    asm("mov.b64 %0, {%1, %1};" : "=l"(o) : "r"(__float_as_uint(f)))

__device__ __forceinline__ uint32_t smem_u32(const void* p) {
    uint32_t a;
    asm("{ .reg .u64 t; cvta.to.shared.u64 t, %1; cvt.u32.u64 %0, t; }"
        : "=r"(a) : "l"(p));
    return a;
}
#define CP_ASYNC16(DST, SRC) \
    asm volatile("cp.async.cg.shared.global [%0], [%1], 16;" \
                 :: "r"(DST), "l"(SRC) : "memory")
#define CP_ASYNC4(DST, SRC) \
    asm volatile("cp.async.ca.shared.global [%0], [%1], 4;" \
                 :: "r"(DST), "l"(SRC) : "memory")
#define CP_COMMIT() asm volatile("cp.async.commit_group;" ::: "memory")
#define CP_WAIT1()  asm volatile("cp.async.wait_group 1;" ::: "memory")
#define CP_WAIT0()  asm volatile("cp.async.wait_group 0;" ::: "memory")

// Fast-math-immune ~1-ulp sigmoid (proved necessary in R3)
__device__ __forceinline__ float sigmoid_acc(float x)
{
    float t = -x;
    t = fminf(fmaxf(t, -80.0f), 80.0f);
    float n = rintf(t * 1.4426950408889634f);
    float r = fmaf(n, -0.693359375f, t);
    r = fmaf(n, 2.12194440e-4f, r);
    float p = 1.9841270e-4f;
    p = fmaf(p, r, 1.3888889e-3f);
    p = fmaf(p, r, 8.3333333e-3f);
    p = fmaf(p, r, 4.1666667e-2f);
    p = fmaf(p, r, 0.16666667f);
    p = fmaf(p, r, 0.5f);
    p = fmaf(p, r, 1.0f);
    p = fmaf(p, r, 1.0f);
    float e = p * __int_as_float(((int)n + 127) << 23);
    return __frcp_rn(1.0f + e);
}

// ---------------------------------------------------------------------------
// Kernel 1: transpose W [256][7168] -> g_Wt [7168][256]
// ---------------------------------------------------------------------------
__global__ void transpose_w(const float* __restrict__ W)
{
    __shared__ float tile[32][33];
    const int k0 = blockIdx.x * 32;
    const int e0 = blockIdx.y * 32;
    const int tx = threadIdx.x, ty = threadIdx.y;   // 32 x 8
    #pragma unroll
    for (int j = 0; j < 4; j++) {
        int e = ty + 8 * j;
        tile[e][tx] = W[(size_t)(e0 + e) * HD + k0 + tx];
    }
    __syncthreads();
    #pragma unroll
    for (int j = 0; j < 4; j++) {
        int k = ty + 8 * j;
        g_Wt[(size_t)(k0 + k) * NE + e0 + tx] = tile[tx][k];
    }
}

// ---------------------------------------------------------------------------
// Kernel 2: fused gate GEMM + routing.
// CTA = 8 tokens x 256 experts, 256 threads, thread tile 1 tok x 8 exp
// (4 f32x2 pairs). 2048 CTAs -> 6.92 tiles/slot @ 2 CTA/SM (1.2% tail).
// Accumulation chain BIT-IDENTICAL to R3/R13: cacc over 32 ascending k,
// mid += cacc per chunk, acc += mid every 8 chunks; same expert pairing.
// B-stages are contiguous 32KB cp.async copies from pre-transposed g_Wt.
// 3-buffer ring, ONE barrier per stage. Routing fused in epilogue.
// ---------------------------------------------------------------------------
__global__ __launch_bounds__(256, 2)
void gemm_route_kernel(const float* __restrict__ X,
                       const float* __restrict__ BIAS,
                       float* __restrict__ out)
{
    extern __shared__ float sm[];
    float* B_s = sm;                      // [3][32][256]
    float* A_s = sm + NBUF * B_ST;        // [3][32][9]
    const uint32_t smbB = smem_u32(B_s);
    const uint32_t smbA = smem_u32(A_s);

    const int tid = threadIdx.x;
    const int lane = tid & 31;
    const int w    = tid >> 5;            // warp: experts w*32 .. +32
    const int tok  = lane & 7;            // thread's token (0..7)
    const int eh   = lane >> 3;           // expert octet within warp (0..3)
    const int t0   = blockIdx.x * BT;
    const int ebase = w * 32 + eh * 8;    // this thread's 8 experts

    // accumulators: 4 f32x2 pairs (experts ebase+2p, ebase+2p+1)
    uint64_t acc[4], mid[4];
    #pragma unroll
    for (int p = 0; p < 4; p++) { acc[p] = 0ull; mid[p] = 0ull; }

    // staging maps
    const int a_tok = tid & 7, a_k = tid >> 3;      // A: 1 float per thread
    const float* a_src = X + (size_t)(t0 + a_tok) * HD + a_k;

    auto issue = [&](int s) {
        const int buf = s % NBUF;
        // B: contiguous 32KB from g_Wt + s*32*256
        const float* bsrc = g_Wt + (size_t)s * B_ST;
        const uint32_t bdst = smbB + buf * B_ST * 4;
        #pragma unroll
        for (int j = 0; j < 8; j++) {
            int c16 = tid + 256 * j;                 // 16B chunk id (0..2047)
            CP_ASYNC16(bdst + c16 * 16, (const char*)bsrc + c16 * 16);
        }
        // A: 256 floats (8 tok x 32 k), 1 per thread, layout [k][9]+tok
        CP_ASYNC4(smbA + (buf * A_ST + a_k * A_ROW + a_tok) * 4,
                  a_src + s * BK);
    };

    // prologue: prefetch stages 0 and 1
    issue(0); CP_COMMIT();
    issue(1); CP_COMMIT();

    for (int s = 0; s < NST; s++) {
        const int buf = s % NBUF;
        if (s + 1 < NST) { CP_WAIT1(); } else { CP_WAIT0(); }
        __syncthreads();

        const float* Ab = A_s + buf * A_ST + tok;
        const float* Bb = B_s + buf * B_ST + ebase;

        // chunk-local cacc, ascending k (R3's exact chain)
        uint64_t cacc[4];
        #pragma unroll
        for (int p = 0; p < 4; p++) cacc[p] = 0ull;

        #pragma unroll
        for (int k = 0; k < BK; k++) {
            uint64_t a2;
            PACK2(a2, Ab[k * A_ROW]);
            const ulonglong2 b01 = *(const ulonglong2*)(Bb + k * NE);
            const ulonglong2 b23 = *(const ulonglong2*)(Bb + k * NE + 4);
            FMA2(cacc[0], a2, b01.x);
            FMA2(cacc[1], a2, b01.y);
            FMA2(cacc[2], a2, b23.x);
            FMA2(cacc[3], a2, b23.y);
        }

        // mid += cacc; fold into acc every 8 chunks (R3 schedule)
        #pragma unroll
        for (int p = 0; p < 4; p++) ADD2(mid[p], cacc[p]);
        if ((s & 7) == 7) {
            #pragma unroll
            for (int p = 0; p < 4; p++) { ADD2(acc[p], mid[p]); mid[p] = 0ull; }
        }

        // prefetch stage s+2 into ring slot (s+2)%3 — safe: nobody reads it
        if (s + 2 < NST) { issue(s + 2); CP_COMMIT(); }
    }

    // ------------------------------------------------------------------
    // Epilogue: logits -> smem S[8][264], then fused routing (R3 ops)
    // ------------------------------------------------------------------
    __syncthreads();
    float* S = sm;                        // reuse ring smem: 8*264 floats
    #pragma unroll
    for (int p = 0; p < 4; p++) {
        S[tok * 264 + ebase + 2 * p]     = __uint_as_float((uint32_t)acc[p]);
        S[tok * 264 + ebase + 2 * p + 1] = __uint_as_float((uint32_t)(acc[p] >> 32));
    }
    __syncthreads();

    // warp w routes token w (8 warps, 8 tokens)
    {
        const unsigned FULL = 0xffffffffu;
        const int tx = lane;
        const int tokg = t0 + w;
        const float* Lrow = S + w * 264;

        float lgv[8], sfc[8];
        #pragma unroll
        for (int g = 0; g < 8; g++) {
            lgv[g] = Lrow[g * 32 + tx];
            sfc[g] = sigmoid_acc(lgv[g]) + __ldg(&BIAS[g * 32 + tx]);
        }

        float gs[8];
        #pragma unroll
        for (int g = 0; g < 8; g++) {
            float m1 = sfc[g], m2 = -3.4e38f;
            #pragma unroll
            for (int off = 16; off > 0; off >>= 1) {
                float o1 = __shfl_xor_sync(FULL, m1, off);
                float o2 = __shfl_xor_sync(FULL, m2, off);
                if (o1 > m1) { m2 = fmaxf(m1, o2); m1 = o1; }
                else         { m2 = fmaxf(m2, o1); }
            }
            gs[g] = m1 + m2;
        }

        unsigned gmask = 0;
        #pragma unroll
        for (int it = 0; it < 4; it++) {
            float best = -3.4e38f; int bg = 0;
            #pragma unroll
            for (int g = 0; g < 8; g++) {
                bool fr = !((gmask >> g) & 1);
                if (fr && gs[g] > best) { best = gs[g]; bg = g; }
            }
            gmask |= (1u << bg);
        }

        float val[8];
        #pragma unroll
        for (int g = 0; g < 8; g++)
            val[g] = ((gmask >> g) & 1) ? sfc[g] : 0.0f;

        float wts[8]; int ids[8]; float wsum = 0.0f;
        #pragma unroll
        for (int k = 0; k < 8; k++) {
            float bv = -3.4e38f; int be = 1 << 30;
            #pragma unroll
            for (int g = 0; g < 8; g++) {
                int e = g * 32 + tx;
                bool better = (val[g] > bv) || (val[g] == bv && e < be);
                if (better) { bv = val[g]; be = e; }
            }
            #pragma unroll
            for (int off = 16; off > 0; off >>= 1) {
                float ov = __shfl_xor_sync(FULL, bv, off);
                int   oe = __shfl_xor_sync(FULL, be, off);
                if (ov > bv || (ov == bv && oe < be)) { bv = ov; be = oe; }
            }
            const int cg = be >> 5, cl = be & 31;
            float sel = lgv[0];
            #pragma unroll
            for (int g = 1; g < 8; g++) if (g == cg) sel = lgv[g];
            float lg = __shfl_sync(FULL, sel, cl);
            float wgt = sigmoid_acc(lg);
            wts[k] = wgt; ids[k] = be; wsum += wgt;
            #pragma unroll
            for (int g = 0; g < 8; g++)
                if (g == cg && tx == cl) val[g] = -3.4e38f;
        }

        if (tx == 0) {
            float denom = wsum + 1e-20f;
            #pragma unroll
            for (int k = 0; k < 8; k++) {
                out[(size_t)tokg * 8 + k] = (float)ids[k];
                out[(size_t)TK * 8 + (size_t)tokg * 8 + k] = (wts[k] / denom) * 2.5f;
            }
        }
    }
}

extern "C" void kernel_launch(void* const* d_in, const int* in_sizes, int n_in,
                              void* d_out, int out_size)
{
    const float* X    = (const float*)d_in[0];   // [4,4096,7168] fp32
    const float* W    = (const float*)d_in[1];   // [256,7168]    fp32
    const float* BIAS = (const float*)d_in[2];   // [256]         fp32
    float* out = (float*)d_out;                  // idx block then weight block

    cudaFuncSetAttribute(gemm_route_kernel,
                         cudaFuncAttributeMaxDynamicSharedMemorySize,
                         SMEM_FLOATS * (int)sizeof(float));

    dim3 tg(HD / 32, NE / 32);
    transpose_w<<<tg, dim3(32, 8)>>>(W);
    gemm_route_kernel<<<TK / BT, 256, SMEM_FLOATS * sizeof(float)>>>(X, BIAS, out);
}

// round 16
// speedup vs baseline: 1.3714x; 1.3714x over previous
#include <cuda_runtime.h>
#include <math.h>
#include <stdint.h>

// Problem constants
#define TK   16384
#define HD   7168
#define NE   256
#define BT   64             // tokens per CTA
#define BE   64             // experts per CTA
#define BK   32             // k per stage (= one fold chunk)
#define NST  (HD / BK)      // 224

// smem: double-buffered A [2][32][68] and B [2][32][68] (floats)
#define AP    68
#define BP    68
#define A_ST  (BK * AP)                  // 2176 floats
#define B_ST  (BK * BP)                  // 2176
#define SMEM_FLOATS (2 * (A_ST + B_ST))  // 8704 floats = 34816 B

static __device__ float g_Wt[(size_t)HD * NE];  // W transposed [k][e], 7.3 MB
static __device__ float g_L[(size_t)TK * NE];   // fp32 logits scratch, 16.8 MB

// ---------------------------------------------------------------------------
#define FMA2(c, a, b) \
    asm("fma.rn.f32x2 %0, %1, %2, %0;" : "+l"(c) : "l"(a), "l"(b))
#define ADD2(c, s) \
    asm("add.rn.f32x2 %0, %1, %0;" : "+l"(c) : "l"(s))
#define PACK2(o, f) \
    asm("mov.b64 %0, {%1, %1};" : "=l"(o) : "r"(__float_as_uint(f)))

__device__ __forceinline__ uint32_t smem_u32(const void* p) {
    uint32_t a;
    asm("{ .reg .u64 t; cvta.to.shared.u64 t, %1; cvt.u32.u64 %0, t; }"
        : "=r"(a) : "l"(p));
    return a;
}
#define CP_ASYNC16(DST, SRC) \
    asm volatile("cp.async.cg.shared.global [%0], [%1], 16;" \
                 :: "r"(DST), "l"(SRC) : "memory")
#define CP_COMMIT() asm volatile("cp.async.commit_group;" ::: "memory")
#define CP_WAIT0()  asm volatile("cp.async.wait_group 0;" ::: "memory")

// Fast-math-immune ~1-ulp sigmoid (proved necessary in R3)
__device__ __forceinline__ float sigmoid_acc(float x)
{
    float t = -x;
    t = fminf(fmaxf(t, -80.0f), 80.0f);
    float n = rintf(t * 1.4426950408889634f);
    float r = fmaf(n, -0.693359375f, t);
    r = fmaf(n, 2.12194440e-4f, r);
    float p = 1.9841270e-4f;
    p = fmaf(p, r, 1.3888889e-3f);
    p = fmaf(p, r, 8.3333333e-3f);
    p = fmaf(p, r, 4.1666667e-2f);
    p = fmaf(p, r, 0.16666667f);
    p = fmaf(p, r, 0.5f);
    p = fmaf(p, r, 1.0f);
    p = fmaf(p, r, 1.0f);
    float e = p * __int_as_float(((int)n + 127) << 23);
    return __frcp_rn(1.0f + e);
}

// ---------------------------------------------------------------------------
// Kernel 1: transpose W [256][7168] -> g_Wt [7168][256]
// ---------------------------------------------------------------------------
__global__ void transpose_w(const float* __restrict__ W)
{
    __shared__ float tile[32][33];
    const int k0 = blockIdx.x * 32;
    const int e0 = blockIdx.y * 32;
    const int tx = threadIdx.x, ty = threadIdx.y;   // 32 x 8
    #pragma unroll
    for (int j = 0; j < 4; j++) {
        int e = ty + 8 * j;
        tile[e][tx] = W[(size_t)(e0 + e) * HD + k0 + tx];
    }
    __syncthreads();
    #pragma unroll
    for (int j = 0; j < 4; j++) {
        int k = ty + 8 * j;
        g_Wt[(size_t)(k0 + k) * NE + e0 + tx] = tile[tx][k];
    }
}

// ---------------------------------------------------------------------------
// Kernel 2: fp32 GEMM via fma.rn.f32x2, chain BIT-IDENTICAL to R3/R13:
// per logit, cacc over 32 ascending k (RN), mid += cacc per chunk,
// acc += mid every 8 chunks.
// CTA 64 tok x 64 exp, 256 threads, thread tile 4 tok x 4 exp (2 f32x2
// pairs x 4 tokens -> 48 chain regs). 2 CTAs/SM = 16 warps (latency hiding).
// B from pre-transposed g_Wt via cp.async (no staging regs); A via
// register-transpose. One barrier + one wait per 32-k stage.
// ---------------------------------------------------------------------------
__global__ __launch_bounds__(256, 2)
void gemm_kernel(const float* __restrict__ X, float* __restrict__ L)
{
    extern __shared__ float sm[];
    float* A_s = sm;                 // [2][32][68]  k-major
    float* B_s = sm + 2 * A_ST;      // [2][32][68]
    const uint32_t smbB = smem_u32(B_s);

    const int tid  = threadIdx.x;
    const int lane = tid & 31;
    const int w    = tid >> 5;       // warp 0..7 -> experts w*8 .. +8
    const int tg   = lane & 15;      // tokens 4tg..4tg+3
    const int eo   = lane >> 4;      // 0/1 -> expert quad within warp
    const int t0   = blockIdx.x * BT;
    const int e0   = blockIdx.y * BE;
    const int ebase = w * 8 + eo * 4;   // local experts ebase..ebase+3

    // chain accumulators: [token][pair], pair p = experts (ebase+2p, +2p+1)
    uint64_t acc[4][2], mid[4][2];
    #pragma unroll
    for (int t = 0; t < 4; t++)
        #pragma unroll
        for (int p = 0; p < 2; p++) { acc[t][p] = 0ull; mid[t][p] = 0ull; }

    // A staging: token atok (0..63), k-octet akseg (0..3) -> 8 floats
    const int atok  = tid >> 2;
    const int akseg = tid & 3;
    const float* arow = X + (size_t)(t0 + atok) * HD + akseg * 8;

    // B staging via cp.async from g_Wt: 512 16B-chunks per stage, 2/thread
    // chunk c: row = c>>4 (k), col16 = c&15 (4 floats)
    auto issueB = [&](int s, int buf) {
        const uint32_t bdst = smbB + buf * B_ST * 4;
        #pragma unroll
        for (int j = 0; j < 2; j++) {
            int c = tid + 256 * j;
            int row = c >> 4, col16 = c & 15;
            const float* src = g_Wt + (size_t)(s * BK + row) * NE + e0 + col16 * 4;
            CP_ASYNC16(bdst + (row * BP + col16 * 4) * 4, src);
        }
    };

    float4 areg[2];
    auto loadA = [&](int s) {
        areg[0] = *(const float4*)(arow + s * BK);
        areg[1] = *(const float4*)(arow + s * BK + 4);
    };
    auto commitA = [&](int buf) {
        float* Ab = A_s + buf * A_ST;
        const int kb = akseg * 8;
        Ab[(kb + 0) * AP + atok] = areg[0].x;
        Ab[(kb + 1) * AP + atok] = areg[0].y;
        Ab[(kb + 2) * AP + atok] = areg[0].z;
        Ab[(kb + 3) * AP + atok] = areg[0].w;
        Ab[(kb + 4) * AP + atok] = areg[1].x;
        Ab[(kb + 5) * AP + atok] = areg[1].y;
        Ab[(kb + 6) * AP + atok] = areg[1].z;
        Ab[(kb + 7) * AP + atok] = areg[1].w;
    };

    // prologue
    issueB(0, 0); CP_COMMIT();
    loadA(0); commitA(0);
    if (NST > 1) loadA(1);

    for (int s = 0; s < NST; s++) {
        const int buf = s & 1;
        CP_WAIT0();                 // B(s) landed (copy overlapped compute(s-1))
        __syncthreads();            // visibility + everyone past compute(s-1)

        // kick next stage into the other buffer (overlaps with compute below)
        if (s + 1 < NST) {
            issueB(s + 1, buf ^ 1); CP_COMMIT();
            commitA(buf ^ 1);
        }

        const float* Ab = A_s + buf * A_ST;
        const float* Bb = B_s + buf * B_ST;

        // chunk-local cacc, ascending k (R3's exact chain)
        uint64_t cacc[4][2];
        #pragma unroll
        for (int t = 0; t < 4; t++)
            #pragma unroll
            for (int p = 0; p < 2; p++) cacc[t][p] = 0ull;

        #pragma unroll
        for (int k = 0; k < BK; k++) {
            const float4 a4 = *(const float4*)(Ab + k * AP + 4 * tg);
            uint64_t a2[4];
            PACK2(a2[0], a4.x); PACK2(a2[1], a4.y);
            PACK2(a2[2], a4.z); PACK2(a2[3], a4.w);
            const ulonglong2 b2 = *(const ulonglong2*)(Bb + k * BP + ebase);
            #pragma unroll
            for (int t = 0; t < 4; t++) {
                FMA2(cacc[t][0], a2[t], b2.x);
                FMA2(cacc[t][1], a2[t], b2.y);
            }
        }

        // mid += cacc; fold into acc every 8 chunks (R3 schedule)
        #pragma unroll
        for (int t = 0; t < 4; t++)
            #pragma unroll
            for (int p = 0; p < 2; p++) ADD2(mid[t][p], cacc[t][p]);
        if ((s & 7) == 7) {
            #pragma unroll
            for (int t = 0; t < 4; t++)
                #pragma unroll
                for (int p = 0; p < 2; p++) { ADD2(acc[t][p], mid[t][p]); mid[t][p] = 0ull; }
        }

        if (s + 2 < NST) loadA(s + 2);
    }

    // epilogue: unpack f32x2 -> logits
    #pragma unroll
    for (int t = 0; t < 4; t++)
        #pragma unroll
        for (int p = 0; p < 2; p++) {
            float* dst = L + (size_t)(t0 + 4 * tg + t) * NE + e0 + ebase + 2 * p;
            dst[0] = __uint_as_float((uint32_t)acc[t][p]);
            dst[1] = __uint_as_float((uint32_t)(acc[t][p] >> 32));
        }
}

// ---------------------------------------------------------------------------
// Kernel 3: routing (ops identical to R3/R13). Warp routes a token.
// ---------------------------------------------------------------------------
__global__ __launch_bounds__(256, 4)
void route_kernel(const float* __restrict__ BIAS, float* __restrict__ out)
{
    const int wid = threadIdx.x >> 5;
    const int tx  = threadIdx.x & 31;
    const unsigned FULL = 0xffffffffu;

    for (int rr = 0; rr < 4; rr++) {
        const int tok = blockIdx.x * 32 + wid * 4 + rr;
        const float* Lrow = g_L + (size_t)tok * NE;

        float lgv[8], sfc[8];
        #pragma unroll
        for (int g = 0; g < 8; g++) {
            lgv[g] = Lrow[g * 32 + tx];
            sfc[g] = sigmoid_acc(lgv[g]) + __ldg(&BIAS[g * 32 + tx]);
        }

        float gs[8];
        #pragma unroll
        for (int g = 0; g < 8; g++) {
            float m1 = sfc[g], m2 = -3.4e38f;
            #pragma unroll
            for (int off = 16; off > 0; off >>= 1) {
                float o1 = __shfl_xor_sync(FULL, m1, off);
                float o2 = __shfl_xor_sync(FULL, m2, off);
                if (o1 > m1) { m2 = fmaxf(m1, o2); m1 = o1; }
                else         { m2 = fmaxf(m2, o1); }
            }
            gs[g] = m1 + m2;
        }

        unsigned gmask = 0;
        #pragma unroll
        for (int it = 0; it < 4; it++) {
            float best = -3.4e38f; int bg = 0;
            #pragma unroll
            for (int g = 0; g < 8; g++) {
                bool fr = !((gmask >> g) & 1);
                if (fr && gs[g] > best) { best = gs[g]; bg = g; }
            }
            gmask |= (1u << bg);
        }

        float val[8];
        #pragma unroll
        for (int g = 0; g < 8; g++)
            val[g] = ((gmask >> g) & 1) ? sfc[g] : 0.0f;

        float wts[8]; int ids[8]; float wsum = 0.0f;
        #pragma unroll
        for (int k = 0; k < 8; k++) {
            float bv = -3.4e38f; int be = 1 << 30;
            #pragma unroll
            for (int g = 0; g < 8; g++) {
                int e = g * 32 + tx;
                bool better = (val[g] > bv) || (val[g] == bv && e < be);
                if (better) { bv = val[g]; be = e; }
            }
            #pragma unroll
            for (int off = 16; off > 0; off >>= 1) {
                float ov = __shfl_xor_sync(FULL, bv, off);
                int   oe = __shfl_xor_sync(FULL, be, off);
                if (ov > bv || (ov == bv && oe < be)) { bv = ov; be = oe; }
            }
            const int cg = be >> 5, cl = be & 31;
            float sel = lgv[0];
            #pragma unroll
            for (int g = 1; g < 8; g++) if (g == cg) sel = lgv[g];
            float lg = __shfl_sync(FULL, sel, cl);
            float wgt = sigmoid_acc(lg);
            wts[k] = wgt; ids[k] = be; wsum += wgt;
            #pragma unroll
            for (int g = 0; g < 8; g++)
                if (g == cg && tx == cl) val[g] = -3.4e38f;
        }

        if (tx == 0) {
            float denom = wsum + 1e-20f;
            #pragma unroll
            for (int k = 0; k < 8; k++) {
                out[(size_t)tok * 8 + k] = (float)ids[k];
                out[(size_t)TK * 8 + (size_t)tok * 8 + k] = (wts[k] / denom) * 2.5f;
            }
        }
    }
}

extern "C" void kernel_launch(void* const* d_in, const int* in_sizes, int n_in,
                              void* d_out, int out_size)
{
    const float* X    = (const float*)d_in[0];   // [4,4096,7168] fp32
    const float* W    = (const float*)d_in[1];   // [256,7168]    fp32
    const float* BIAS = (const float*)d_in[2];   // [256]         fp32
    float* out = (float*)d_out;                  // idx block then weight block

    cudaFuncSetAttribute(gemm_kernel,
                         cudaFuncAttributeMaxDynamicSharedMemorySize,
                         SMEM_FLOATS * (int)sizeof(float));

    void* lptr = nullptr;
    cudaGetSymbolAddress(&lptr, g_L);
    float* L = (float*)lptr;

    dim3 tg(HD / 32, NE / 32);
    transpose_w<<<tg, dim3(32, 8)>>>(W);
    dim3 grid(TK / BT, NE / BE);
    gemm_kernel<<<grid, 256, SMEM_FLOATS * sizeof(float)>>>(X, L);
    route_kernel<<<TK / 32, 256>>>(BIAS, out);
}